// round 6
// baseline (speedup 1.0000x reference)
#include <cuda_runtime.h>
#include <cuda_bf16.h>

typedef unsigned long long ULL;

// Problem constants (fixed by setup_inputs)
#define IH 2160
#define IW 3840
#define HW (IH * IW)
#define KS 25
#define PADK 12
#define LH (IH + 22)
#define LW (IW + 22)
#define L3 (3 * LH * LW)

// Blur tiling: 32 cols x 64 rows per block; each thread covers rows (lane, lane+32)
#define TILE_X 32
#define TILE_Y 64
#define SROWS 88           // 64 + 24 halo       (type A: ch0/ch1 packed)
#define SPROWS 56          // pair rows          (type B: ch2 rows (r, r+32))
#define SCOLS 56           // 32 + 24 halo
#define SSTRIDE 57
#define BLK_THREADS 128    // 4 warps x 8 cols, lane = row index

#define SPK_ELEMS (SROWS * SSTRIDE)                 // float2 (type A tile, superset)
#define SWT_ELEMS (KS * KS)                         // float2 duplicated weights
#define SMEM_BYTES ((SPK_ELEMS + SWT_ELEMS) * 8)    // 45,128 B -> 5 blocks/SM

// Laplacian
#define LAP_ROWS (3 * LH)            // 6546
#define LAP_THREADS 256
#define LAP_VCHUNKS 958              // vector chunks: ox = 15 + 4c, c < 958
__device__ float g_partials[LAP_ROWS];

__device__ __forceinline__ int clampi(int v, int lo, int hi) {
    return min(max(v, lo), hi);
}

// ---------------------------------------------------------------------------
// Kernel 1: 25x25 depthwise blur, edge-replicate pad, + noise. All FFMA2.
// gridDim.z = 2:
//   z==0 (type A): ch0,ch1 packed as f32x2; thread computes rows y0=lane, y1=lane+32.
//   z==1 (type B): ch2 rows (y0,y1) packed as f32x2 via pair tile s2p[r]=(in2[r],in2[r+32]).
// Weights pre-duplicated in smem (LDS.64 broadcast). Rotating register windows.
// ---------------------------------------------------------------------------
__global__ void __launch_bounds__(BLK_THREADS, 5)
blur_kernel(const float* __restrict__ img,
            const float* __restrict__ noise,
            const float* __restrict__ g,
            float* __restrict__ out)
{
    extern __shared__ float2 smem[];
    float2* tile = smem;                 // A: [88 x 57]  B: [56 x 57] (prefix)
    float2* swt2 = smem + SPK_ELEMS;     // duplicated weights [625]

    const int tx0 = blockIdx.x * TILE_X;
    const int ty0 = blockIdx.y * TILE_Y;
    const int tid = threadIdx.x;

    // duplicated weights
    for (int i = tid; i < SWT_ELEMS; i += BLK_THREADS) {
        float w = g[i];
        swt2[i] = make_float2(w, w);
    }

    const int lane = tid & 31;      // row index within tile (y0 = ty0+lane)
    const int wid  = tid >> 5;      // x-group (0..3)
    const int xb   = wid * 8;       // column base within tile
    const int x    = tx0 + xb;

    if (blockIdx.z == 0) {
        // ---------------- Type A: channels 0,1 ----------------
        for (int i = tid; i < SROWS * SCOLS; i += BLK_THREADS) {
            int r = i / SCOLS, c = i % SCOLS;
            int gy = clampi(ty0 - PADK + r, 0, IH - 1);
            int gx = clampi(tx0 - PADK + c, 0, IW - 1);
            int gi = gy * IW + gx;
            tile[r * SSTRIDE + c] = make_float2(img[gi], img[HW + gi]);
        }
        __syncthreads();

        ULL acc0[8], acc1[8];
#pragma unroll
        for (int j = 0; j < 8; j++) { acc0[j] = 0ull; acc1[j] = 0ull; }

#pragma unroll 1
        for (int ky = 0; ky < KS; ++ky) {
            const ULL* r0 = reinterpret_cast<const ULL*>(tile + (lane + ky) * SSTRIDE + xb);
            const ULL* r1 = reinterpret_cast<const ULL*>(tile + (lane + 32 + ky) * SSTRIDE + xb);
            const ULL* wp = reinterpret_cast<const ULL*>(swt2 + ky * KS);

            ULL a[8], b[8];
#pragma unroll
            for (int j = 0; j < 8; j++) { a[j] = r0[j]; b[j] = r1[j]; }

#pragma unroll
            for (int kx = 0; kx < KS; ++kx) {
                ULL ww = wp[kx];                       // LDS.64 uniform broadcast
#pragma unroll
                for (int j = 0; j < 8; j++) {
                    const int s = (kx + j) & 7;        // rotating slot
                    asm("fma.rn.f32x2 %0, %1, %2, %0;" : "+l"(acc0[j]) : "l"(a[s]), "l"(ww));
                    asm("fma.rn.f32x2 %0, %1, %2, %0;" : "+l"(acc1[j]) : "l"(b[s]), "l"(ww));
                }
                if (kx < KS - 1) {
                    const int s = kx & 7;
                    a[s] = r0[8 + kx];
                    b[s] = r1[8 + kx];
                }
            }
        }

        {   // row y0 (always valid)
            const int base = (ty0 + lane) * IW + x;
            float4 n0 = *reinterpret_cast<const float4*>(noise + base);
            float4 n1 = *reinterpret_cast<const float4*>(noise + base + 4);
            float v0[8], v1[8];
#pragma unroll
            for (int j = 0; j < 8; j++) {
                float2 f = *reinterpret_cast<float2*>(&acc0[j]);
                v0[j] = f.x; v1[j] = f.y;
            }
            *reinterpret_cast<float4*>(out + 0 * HW + base) =
                make_float4(v0[0] + n0.x, v0[1] + n0.y, v0[2] + n0.z, v0[3] + n0.w);
            *reinterpret_cast<float4*>(out + 0 * HW + base + 4) =
                make_float4(v0[4] + n1.x, v0[5] + n1.y, v0[6] + n1.z, v0[7] + n1.w);
            *reinterpret_cast<float4*>(out + 1 * HW + base) =
                make_float4(v1[0] + n0.x, v1[1] + n0.y, v1[2] + n0.z, v1[3] + n0.w);
            *reinterpret_cast<float4*>(out + 1 * HW + base + 4) =
                make_float4(v1[4] + n1.x, v1[5] + n1.y, v1[6] + n1.z, v1[7] + n1.w);
        }
        const int y1 = ty0 + lane + 32;
        if (y1 < IH) {
            const int base = y1 * IW + x;
            float4 n0 = *reinterpret_cast<const float4*>(noise + base);
            float4 n1 = *reinterpret_cast<const float4*>(noise + base + 4);
            float v0[8], v1[8];
#pragma unroll
            for (int j = 0; j < 8; j++) {
                float2 f = *reinterpret_cast<float2*>(&acc1[j]);
                v0[j] = f.x; v1[j] = f.y;
            }
            *reinterpret_cast<float4*>(out + 0 * HW + base) =
                make_float4(v0[0] + n0.x, v0[1] + n0.y, v0[2] + n0.z, v0[3] + n0.w);
            *reinterpret_cast<float4*>(out + 0 * HW + base + 4) =
                make_float4(v0[4] + n1.x, v0[5] + n1.y, v0[6] + n1.z, v0[7] + n1.w);
            *reinterpret_cast<float4*>(out + 1 * HW + base) =
                make_float4(v1[0] + n0.x, v1[1] + n0.y, v1[2] + n0.z, v1[3] + n0.w);
            *reinterpret_cast<float4*>(out + 1 * HW + base + 4) =
                make_float4(v1[4] + n1.x, v1[5] + n1.y, v1[6] + n1.z, v1[7] + n1.w);
        }
    } else {
        // ---------------- Type B: channel 2, row pairs ----------------
        const float* img2 = img + 2 * HW;
        for (int i = tid; i < SPROWS * SCOLS; i += BLK_THREADS) {
            int r = i / SCOLS, c = i % SCOLS;
            int gx  = clampi(tx0 - PADK + c, 0, IW - 1);
            int gy0 = clampi(ty0 - PADK + r,      0, IH - 1);
            int gy1 = clampi(ty0 - PADK + r + 32, 0, IH - 1);
            tile[r * SSTRIDE + c] = make_float2(img2[gy0 * IW + gx], img2[gy1 * IW + gx]);
        }
        __syncthreads();

        ULL acc2[8];
#pragma unroll
        for (int j = 0; j < 8; j++) acc2[j] = 0ull;

#pragma unroll 1
        for (int ky = 0; ky < KS; ++ky) {
            const ULL* p2 = reinterpret_cast<const ULL*>(tile + (lane + ky) * SSTRIDE + xb);
            const ULL* wp = reinterpret_cast<const ULL*>(swt2 + ky * KS);

            ULL c[8];
#pragma unroll
            for (int j = 0; j < 8; j++) c[j] = p2[j];

#pragma unroll
            for (int kx = 0; kx < KS; ++kx) {
                ULL ww = wp[kx];
#pragma unroll
                for (int j = 0; j < 8; j++) {
                    const int s = (kx + j) & 7;
                    asm("fma.rn.f32x2 %0, %1, %2, %0;" : "+l"(acc2[j]) : "l"(c[s]), "l"(ww));
                }
                if (kx < KS - 1)
                    c[kx & 7] = p2[8 + kx];
            }
        }

        {   // row y0
            const int base = (ty0 + lane) * IW + x;
            float4 n0 = *reinterpret_cast<const float4*>(noise + base);
            float4 n1 = *reinterpret_cast<const float4*>(noise + base + 4);
            float v[8];
#pragma unroll
            for (int j = 0; j < 8; j++) v[j] = reinterpret_cast<float2*>(&acc2[j])->x;
            *reinterpret_cast<float4*>(out + 2 * HW + base) =
                make_float4(v[0] + n0.x, v[1] + n0.y, v[2] + n0.z, v[3] + n0.w);
            *reinterpret_cast<float4*>(out + 2 * HW + base + 4) =
                make_float4(v[4] + n1.x, v[5] + n1.y, v[6] + n1.z, v[7] + n1.w);
        }
        const int y1 = ty0 + lane + 32;
        if (y1 < IH) {
            const int base = y1 * IW + x;
            float4 n0 = *reinterpret_cast<const float4*>(noise + base);
            float4 n1 = *reinterpret_cast<const float4*>(noise + base + 4);
            float v[8];
#pragma unroll
            for (int j = 0; j < 8; j++) v[j] = reinterpret_cast<float2*>(&acc2[j])->y;
            *reinterpret_cast<float4*>(out + 2 * HW + base) =
                make_float4(v[0] + n0.x, v[1] + n0.y, v[2] + n0.z, v[3] + n0.w);
            *reinterpret_cast<float4*>(out + 2 * HW + base + 4) =
                make_float4(v[4] + n1.x, v[5] + n1.y, v[6] + n1.z, v[7] + n1.w);
        }
    }
}

// ---------------------------------------------------------------------------
// Kernel 2: Laplacian (3x3, pad=12 replicate), squared, per-row partial sums.
// ---------------------------------------------------------------------------
__global__ void __launch_bounds__(LAP_THREADS)
lap_kernel(const float* __restrict__ img)
{
    const int row = blockIdx.x;          // 0 .. LAP_ROWS-1
    const int ch  = row / LH;
    const int oy  = row - ch * LH;
    const float* p = img + ch * HW;

    const int ru = clampi(oy - 12, 0, IH - 1);
    const int rc = clampi(oy - 11, 0, IH - 1);
    const int rd = clampi(oy - 10, 0, IH - 1);
    const float* __restrict__ pu = p + ru * IW;
    const float* __restrict__ pc = p + rc * IW;
    const float* __restrict__ pd = p + rd * IW;

    float acc = 0.0f;

    // vector interior: cc0 = 4 + 4c (16B aligned)
    for (int c = threadIdx.x; c < LAP_VCHUNKS; c += LAP_THREADS) {
        int cc0 = 4 + 4 * c;
        float4 u = *reinterpret_cast<const float4*>(pu + cc0);
        float4 m = *reinterpret_cast<const float4*>(pc + cc0);
        float4 d = *reinterpret_cast<const float4*>(pd + cc0);
        float l = pc[cc0 - 1];
        float r = pc[cc0 + 4];
        float v0 = 4.0f * m.x - u.x - d.x - l   - m.y;
        float v1 = 4.0f * m.y - u.y - d.y - m.x - m.z;
        float v2 = 4.0f * m.z - u.z - d.z - m.y - m.w;
        float v3 = 4.0f * m.w - u.w - d.w - m.z - r;
        acc = fmaf(v0, v0, acc);
        acc = fmaf(v1, v1, acc);
        acc = fmaf(v2, v2, acc);
        acc = fmaf(v3, v3, acc);
    }

    // scalar edges: ox in [0,14] and [3847, 3861]
    if (threadIdx.x < 30) {
        int t = threadIdx.x;
        int ox = (t < 15) ? t : (3832 + t);
        int cl = clampi(ox - 12, 0, IW - 1);
        int cc = clampi(ox - 11, 0, IW - 1);
        int cr = clampi(ox - 10, 0, IW - 1);
        float v = 4.0f * pc[cc] - pu[cc] - pd[cc] - pc[cl] - pc[cr];
        acc = fmaf(v, v, acc);
    }

    __shared__ float sbuf[LAP_THREADS];
    sbuf[threadIdx.x] = acc;
    __syncthreads();
#pragma unroll
    for (int s = LAP_THREADS / 2; s > 0; s >>= 1) {
        if (threadIdx.x < s) sbuf[threadIdx.x] += sbuf[threadIdx.x + s];
        __syncthreads();
    }
    if (threadIdx.x == 0) g_partials[row] = sbuf[0];
}

// ---------------------------------------------------------------------------
// Kernel 3: final deterministic reduction in double -> mean scalar.
// ---------------------------------------------------------------------------
__global__ void __launch_bounds__(256)
reduce_kernel(float* __restrict__ out_scalar)
{
    __shared__ double sd[256];
    double s = 0.0;
    for (int i = threadIdx.x; i < LAP_ROWS; i += 256) s += (double)g_partials[i];
    sd[threadIdx.x] = s;
    __syncthreads();
#pragma unroll
    for (int k = 128; k > 0; k >>= 1) {
        if (threadIdx.x < k) sd[threadIdx.x] += sd[threadIdx.x + k];
        __syncthreads();
    }
    if (threadIdx.x == 0)
        out_scalar[0] = (float)(sd[0] / (double)L3);
}

extern "C" void kernel_launch(void* const* d_in, const int* in_sizes, int n_in,
                              void* d_out, int out_size)
{
    const float* img   = (const float*)d_in[0];  // (1,3,2160,3840)
    const float* noise = (const float*)d_in[1];  // (1,1,2160,3840)
    const float* g     = (const float*)d_in[2];  // (25,25)
    float* out = (float*)d_out;                  // [3*H*W conv output, 1 scalar]

    static bool attr_set = false;
    if (!attr_set) {
        cudaFuncSetAttribute(blur_kernel,
                             cudaFuncAttributeMaxDynamicSharedMemorySize, SMEM_BYTES);
        attr_set = true;
    }

    dim3 gridB(IW / TILE_X, (IH + TILE_Y - 1) / TILE_Y, 2);   // 120 x 34 x 2
    blur_kernel<<<gridB, BLK_THREADS, SMEM_BYTES>>>(img, noise, g, out);

    lap_kernel<<<LAP_ROWS, LAP_THREADS>>>(img);
    reduce_kernel<<<1, 256>>>(out + (out_size - 1));
}